// round 17
// baseline (speedup 1.0000x reference)
#include <cuda_runtime.h>
#include <cstdint>

// Problem sizes (fixed by the reference)
#define B_N 8
#define L_N 4096
#define F_N 64

#define TILE_M 128
#define KC 32                    // k floats per chunk = 128 B per adj row
#define KSPLIT 2
#define KHALF (L_N / KSPLIT)     // 2048
#define NCHUNK (KHALF / KC)      // 64
#define STAGES 3

#define A_STAGE 16384            // 128 rows x 128 B, XOR-swizzled 16B chunks
#define SMEM_BYTES (STAGES * A_STAGE)   // 49152 -> 4 CTAs/SM

// hidden, packed for LDG.128 B-fragment loads:
// float offset = (kb*4 + j)*128 + group*16 + tig*4 + (nt&1)*2 + p   (+ b*512*512)
// where for element (b, l, o): kb=l>>3, kr=l&7, tig=kr&3, p=kr>>2,
//                              nt=o>>3, j=nt>>1, group=o&7
__device__ float g_hiddenP[(size_t)B_N * 512 * 512];
// split-K partial sums
__device__ float g_part[KSPLIT][(size_t)B_N * L_N * F_N];

// ---------------------------------------------------------------------------
// helpers
// ---------------------------------------------------------------------------
__device__ __forceinline__ uint32_t smem_u32(const void* p) {
    uint32_t a;
    asm("{ .reg .u64 t; cvta.to.shared.u64 t, %1; cvt.u32.u64 %0, t; }" : "=r"(a) : "l"(p));
    return a;
}

__device__ __forceinline__ void cp16(uint32_t dst, const void* src) {
    asm volatile("cp.async.cg.shared.global [%0], [%1], 16;" :: "r"(dst), "l"(src) : "memory");
}

__device__ __forceinline__ void mma_tf32(float* c, uint32_t a0, uint32_t a1,
                                         uint32_t a2, uint32_t a3,
                                         uint32_t b0, uint32_t b1) {
    asm volatile(
        "mma.sync.aligned.m16n8k8.row.col.f32.tf32.tf32.f32 "
        "{%0,%1,%2,%3}, {%4,%5,%6,%7}, {%8,%9}, {%0,%1,%2,%3};"
        : "+f"(c[0]), "+f"(c[1]), "+f"(c[2]), "+f"(c[3])
        : "r"(a0), "r"(a1), "r"(a2), "r"(a3), "r"(b0), "r"(b1));
}

__device__ __forceinline__ float lds_f(const char* p) {
    return *reinterpret_cast<const float*>(p);
}

// ---------------------------------------------------------------------------
// Kernel A: hidden = text @ W, written tf32-rounded into LDG.128-packed layout
// ---------------------------------------------------------------------------
__global__ void __launch_bounds__(256) hidden_kernel(const float* __restrict__ text,
                                                     const float* __restrict__ weight) {
    __shared__ float s_text[64][65];
    __shared__ float s_w[64][64];
    const int b = blockIdx.y;
    const int l0 = blockIdx.x * 64;
    const int t = threadIdx.x;

    const float* tp = text + ((size_t)b * L_N + l0) * F_N;
#pragma unroll
    for (int j = 0; j < 16; j++) {
        int idx = j * 256 + t;  // 0..4095
        s_text[idx >> 6][idx & 63] = tp[idx];
        s_w[idx >> 6][idx & 63] = weight[idx];
    }
    __syncthreads();

    const int l = t & 63;
    const int og = t >> 6;  // 0..3 -> o = og*16 + i
    float acc[16];
#pragma unroll
    for (int i = 0; i < 16; i++) acc[i] = 0.0f;

    for (int f = 0; f < 64; f++) {
        float tv = s_text[l][f];
#pragma unroll
        for (int i = 0; i < 16; i++) acc[i] += tv * s_w[f][og * 16 + i];
    }

    const int lg = l0 + l;
    const int kb = lg >> 3;
    const int kr = lg & 7;
    const int tig = kr & 3;
    const int p = kr >> 2;
    float* dst = g_hiddenP + ((size_t)b * 512 + kb) * 512 + tig * 4 + p;
#pragma unroll
    for (int i = 0; i < 16; i++) {
        int o = og * 16 + i;
        int nt = o >> 3, j = nt >> 1, group = o & 7;
        uint32_t u;
        asm("cvt.rna.tf32.f32 %0, %1;" : "=r"(u) : "f"(acc[i]));
        dst[j * 128 + group * 16 + (nt & 1) * 2] = __uint_as_float(u);
    }
}

// ---------------------------------------------------------------------------
// Kernel B: g_part[kz][b] = adj[b][:, kz-half] @ hidden[b][kz-half]
// Split-K=2: grid (32, 8, 2), 128 threads (4 warps), 128x64 CTA tile,
// warp tile 32x64, mma.sync tf32. 3 stages x 16KB -> 4 CTAs/SM (16 warps/SM)
// to cover LDS/LDG dependency latency. B frags via LDG.128, double-buffered.
// ---------------------------------------------------------------------------
__global__ void __launch_bounds__(128, 4) gemm_kernel(const float* __restrict__ adj) {
    extern __shared__ char smem[];
    const uint32_t sb = smem_u32(smem);

    const int t = threadIdx.x;
    const int w = t >> 5;         // 0..3
    const int lane = t & 31;
    const int group = lane >> 2;  // 0..7
    const int tig = lane & 3;     // 0..3
    const int b = blockIdx.y;
    const int m0 = blockIdx.x * TILE_M;
    const int kz = blockIdx.z;

    const float* aG = adj + ((size_t)b * L_N + m0) * L_N + kz * KHALF;
    // B fragment base for this lane (k8-blocks of this half start at kz*256)
    const float* bF = g_hiddenP + (size_t)b * 512 * 512 + (size_t)kz * 256 * 512 +
                      group * 16 + tig * 4;

    // ---- CTA-wide cp.async stage issue: 128 rows x 128B, swizzled ----
    auto issueA = [&](int chunk, int slot) {
        uint32_t as = sb + slot * A_STAGE;
        const float* src = aG + chunk * KC;
#pragma unroll
        for (int j = 0; j < 8; j++) {
            int q = j * 128 + t;         // 0..1023
            int row = q >> 3, seg = q & 7;
            cp16(as + row * 128 + ((seg ^ (row & 7)) << 4),
                 src + (size_t)row * L_N + seg * 4);
        }
    };

    // B fragment load: local k8-block index kb (0..255) -> 4 float4
#define LOADB(dst, kb)                                                         \
    {                                                                          \
        const float* _p = bF + (size_t)(kb) * 512;                             \
        (dst)[0] = __ldg(reinterpret_cast<const float4*>(_p));                 \
        (dst)[1] = __ldg(reinterpret_cast<const float4*>(_p + 128));           \
        (dst)[2] = __ldg(reinterpret_cast<const float4*>(_p + 256));           \
        (dst)[3] = __ldg(reinterpret_cast<const float4*>(_p + 384));           \
    }

    float acc[2][8][4];
#pragma unroll
    for (int mt = 0; mt < 2; mt++)
#pragma unroll
        for (int nt = 0; nt < 8; nt++)
#pragma unroll
            for (int r = 0; r < 4; r++) acc[mt][nt][r] = 0.0f;

    issueA(0, 0);
    asm volatile("cp.async.commit_group;" ::: "memory");
    issueA(1, 1);
    asm volatile("cp.async.commit_group;" ::: "memory");

    float4 bq0[4], bq1[4];
    LOADB(bq0, 0);

    for (int i = 0; i < NCHUNK; i++) {
        asm volatile("cp.async.wait_group 1;" ::: "memory");
        __syncthreads();

        if (i + 2 < NCHUNK) issueA(i + 2, (i + 2) % STAGES);
        asm volatile("cp.async.commit_group;" ::: "memory");

        const char* as = smem + (i % STAGES) * A_STAGE;

#pragma unroll
        for (int s = 0; s < 4; s++) {
            const int g = i * 4 + s;
            const int pkb = (g + 1 < NCHUNK * 4) ? g + 1 : g;  // next k8-block
            if (s & 1) { LOADB(bq0, pkb); }
            else       { LOADB(bq1, pkb); }
            const float4* cur = (s & 1) ? bq1 : bq0;

            const int c0 = ((2 * s) ^ group) << 4;
            const int c1 = ((2 * s + 1) ^ group) << 4;
#pragma unroll
            for (int mt = 0; mt < 2; mt++) {
                const int r0 = w * 32 + mt * 16 + group;
                const char* rp = as + r0 * 128;
                uint32_t a0 = __float_as_uint(lds_f(rp + c0 + tig * 4));
                uint32_t a2 = __float_as_uint(lds_f(rp + c1 + tig * 4));
                uint32_t a1 = __float_as_uint(lds_f(rp + 8 * 128 + c0 + tig * 4));
                uint32_t a3 = __float_as_uint(lds_f(rp + 8 * 128 + c1 + tig * 4));
#pragma unroll
                for (int jj = 0; jj < 4; jj++) {
                    mma_tf32(acc[mt][2 * jj], a0, a1, a2, a3,
                             __float_as_uint(cur[jj].x), __float_as_uint(cur[jj].y));
                    mma_tf32(acc[mt][2 * jj + 1], a0, a1, a2, a3,
                             __float_as_uint(cur[jj].z), __float_as_uint(cur[jj].w));
                }
            }
        }
    }

    // ---- epilogue: write partial (no bias; combine adds it) ----
    float* part = g_part[kz];
#pragma unroll
    for (int mt = 0; mt < 2; mt++) {
        const int r0 = m0 + w * 32 + mt * 16 + group;
        float* op0 = part + ((size_t)b * L_N + r0) * F_N;
        float* op1 = op0 + 8 * F_N;
#pragma unroll
        for (int jj = 0; jj < 4; jj++) {
#pragma unroll
            for (int h = 0; h < 2; h++) {
                const int nt = 2 * jj + h;
                const int col = nt * 8 + tig * 2;
                *reinterpret_cast<float2*>(op0 + col) =
                    make_float2(acc[mt][nt][0], acc[mt][nt][1]);
                *reinterpret_cast<float2*>(op1 + col) =
                    make_float2(acc[mt][nt][2], acc[mt][nt][3]);
            }
        }
    }
}

// ---------------------------------------------------------------------------
// Kernel C: out = part0 + part1 + bias
// ---------------------------------------------------------------------------
__global__ void __launch_bounds__(256) combine_kernel(const float* __restrict__ bias,
                                                      float* __restrict__ out) {
    const int idx4 = blockIdx.x * 256 + threadIdx.x;   // float4 index, 524288 total
    const float4 p0 = __ldg(reinterpret_cast<const float4*>(g_part[0]) + idx4);
    const float4 p1 = __ldg(reinterpret_cast<const float4*>(g_part[1]) + idx4);
    const float4 bv = __ldg(reinterpret_cast<const float4*>(bias) + (idx4 & 15));
    float4 r;
    r.x = p0.x + p1.x + bv.x;
    r.y = p0.y + p1.y + bv.y;
    r.z = p0.z + p1.z + bv.z;
    r.w = p0.w + p1.w + bv.w;
    reinterpret_cast<float4*>(out)[idx4] = r;
}

// ---------------------------------------------------------------------------
// launch
// ---------------------------------------------------------------------------
extern "C" void kernel_launch(void* const* d_in, const int* in_sizes, int n_in,
                              void* d_out, int out_size) {
    const float* text = (const float*)d_in[0];   // [8,4096,64]
    const float* adj = (const float*)d_in[1];    // [8,4096,4096]
    const float* weight = (const float*)d_in[2]; // [64,64]
    const float* bias = (const float*)d_in[3];   // [64]
    float* out = (float*)d_out;                  // [8,4096,64]

    cudaFuncSetAttribute(gemm_kernel, cudaFuncAttributeMaxDynamicSharedMemorySize,
                         SMEM_BYTES);

    hidden_kernel<<<dim3(L_N / 64, B_N), 256>>>(text, weight);
    gemm_kernel<<<dim3(L_N / TILE_M, B_N, KSPLIT), 128, SMEM_BYTES>>>(adj);
    combine_kernel<<<(B_N * L_N * F_N / 4) / 256, 256>>>(bias, out);
}